// round 8
// baseline (speedup 1.0000x reference)
#include <cuda_runtime.h>
#include <math.h>

#define N_LOC 4096
#define N_REP 128
#define M_NBR 48
#define NT 544                    // 528 tile owners + 16 spare
#define PBS 20                    // panel buffer row stride (floats)

// smem layout (floats)
#define OFF_PRAW 0
#define OFF_PSOL (OFF_PRAW + 128 * PBS)
#define OFF_XS   (OFF_PSOL + 128 * PBS)
#define OFF_DIAG (OFF_XS + M_NBR * 128)
#define OFF_INVD (OFF_DIAG + 128)
#define OFF_INVL (OFF_INVD + 16)
#define OFF_SCAL (OFF_INVL + 16 * 17)
#define SMEM_FLOATS (OFF_SCAL + 48)

__device__ __forceinline__ void tridec(int t, int& row, int& col) {
    int r = (int)((sqrtf(8.0f * (float)t + 1.0f) - 1.0f) * 0.5f);
    while ((r + 1) * (r + 2) / 2 <= t) ++r;
    while (r * (r + 1) / 2 > t) --r;
    row = r;
    col = t - r * (r + 1) / 2;
}

__global__ __launch_bounds__(NT, 2)
void otm_fused_kernel(const float* __restrict__ aug,
                      const float* __restrict__ theta,
                      const float* __restrict__ scales,
                      const float* __restrict__ nug_mean,
                      const int* __restrict__ batch_idx,
                      float* __restrict__ out)
{
    const int N = blockIdx.x;
    const int tid = threadIdx.x;

    float* g_out = out + (size_t)N * 16384;
    float* c_out = out + (size_t)N_LOC * 16384 + (size_t)N * 16384;

    if (batch_idx[N] == 0) {
        for (int idx = tid; idx < 16384; idx += NT) {
            float v = ((idx >> 7) == (idx & 127)) ? 1.0f : 0.0f;
            g_out[idx] = v;
            c_out[idx] = v;
        }
        return;
    }

    extern __shared__ float smem[];
    float* praw  = smem + OFF_PRAW;   // [128][PBS] raw panel staging
    float* psol  = smem + OFF_PSOL;   // [128][PBS] solved panel / factored diag
    float* xs    = smem + OFF_XS;     // [48][128] k-major
    float* diag  = smem + OFF_DIAG;   // [128]
    float* invd  = smem + OFF_INVD;   // [16]
    float* invL  = smem + OFF_INVL;   // [16][17]
    float* scalm = smem + OFF_SCAL;   // [48]

    const float t2 = theta[2];
    const float t3 = theta[3];
    const float t4 = theta[4];
    const float t5 = theta[5];
    const float ls = expf(t5) * 1.7320508075688772f;
    const float inv_ls2 = 1.0f / (ls * ls);
    const float sig2 = expf(2.0f * (logf(scales[N]) * t4 + t3));
    const float inv_nug = 1.0f / nug_mean[N];

    if (tid < M_NBR) {
        scalm[tid] = expf(-0.5f * (float)(tid + 1) * expf(t2));
    }
    __syncthreads();

    // ---- load xs[m][i] = clean(aug[i,N,1+m]) * scalm[m] ----
    {
        const float* base = aug + (size_t)N * (M_NBR + 1) + 1;
        for (int idx = tid; idx < N_REP * M_NBR; idx += NT) {
            int i = idx / M_NBR;
            int m = idx - i * M_NBR;
            float v = base[(size_t)i * ((size_t)N_LOC * (M_NBR + 1)) + m];
            if (v != v) v = 0.0f;
            xs[m * 128 + i] = v * scalm[m];
        }
    }
    __syncthreads();

    // ---- diag[i] = sum_m xs[m][i]^2 ----
    if (tid < N_REP) {
        float d = 0.0f;
        #pragma unroll
        for (int m = 0; m < M_NBR; ++m) {
            float v = xs[m * 128 + tid];
            d = fmaf(v, v, d);
        }
        diag[tid] = d;
    }
    __syncthreads();

    // ---- tile ownership: tid < 528 owns lower-triangle 4x4 tile (ti,tj) ----
    const bool owner = (tid < 528);
    int ti = 0, tj = 0;
    if (owner) tridec(tid, ti, tj);
    const int ib = ti * 4, jb = tj * 4;
    const int tiblk = ti >> 2, tjblk = tj >> 2;

    float acc[16];
    #pragma unroll
    for (int k = 0; k < 16; ++k) acc[k] = 0.0f;

    if (owner) {
        // ---- Gram in registers ----
        #pragma unroll 4
        for (int m = 0; m < M_NBR; ++m) {
            const float* row = xs + m * 128;
            float4 a = *reinterpret_cast<const float4*>(row + ib);
            float4 b = *reinterpret_cast<const float4*>(row + jb);
            float av[4] = {a.x, a.y, a.z, a.w};
            float bv[4] = {b.x, b.y, b.z, b.w};
            #pragma unroll
            for (int r = 0; r < 4; ++r)
                #pragma unroll
                for (int c = 0; c < 4; ++c)
                    acc[r * 4 + c] = fmaf(av[r], bv[c], acc[r * 4 + c]);
        }

        // ---- epilogue (all 16, symmetric formula) ----
        float di[4], dj[4];
        #pragma unroll
        for (int r = 0; r < 4; ++r) di[r] = diag[ib + r];
        #pragma unroll
        for (int c = 0; c < 4; ++c) dj[c] = diag[jb + c];
        #pragma unroll
        for (int r = 0; r < 4; ++r)
            #pragma unroll
            for (int c = 0; c < 4; ++c) {
                float G = acc[r * 4 + c];
                float sq = fmaxf((di[r] + dj[c] - 2.0f * G) * inv_ls2, 0.0f);
                float s3 = 1.7320508075688772f * sq * __frsqrt_rn(fmaxf(sq, 1e-30f));
                float mat = (1.0f + s3) * __expf(-s3);
                float v = (G + sig2 * mat) * inv_nug
                        + ((ib + r == jb + c) ? 1.0f : 0.0f);
                acc[r * 4 + c] = v;
            }

        // ---- write g straight from registers ----
        #pragma unroll
        for (int r = 0; r < 4; ++r)
            *reinterpret_cast<float4*>(g_out + (ib + r) * 128 + jb) =
                make_float4(acc[r * 4], acc[r * 4 + 1], acc[r * 4 + 2], acc[r * 4 + 3]);
        if (ti > tj) {
            #pragma unroll
            for (int c = 0; c < 4; ++c)
                *reinterpret_cast<float4*>(g_out + (jb + c) * 128 + ib) =
                    make_float4(acc[c], acc[4 + c], acc[8 + c], acc[12 + c]);
        }
    }

    // ================= Cholesky, NB=16, tiles register-resident ==========
    #pragma unroll 1
    for (int kb = 0; kb < 8; ++kb) {
        const int k0 = kb * 16;

        // --- step1: panel owners stage current tiles into praw ---
        if (owner && tjblk == kb) {
            const int co = jb - k0;
            #pragma unroll
            for (int r = 0; r < 4; ++r)
                *reinterpret_cast<float4*>(&praw[(ib + r) * PBS + co]) =
                    make_float4(acc[r * 4], acc[r * 4 + 1], acc[r * 4 + 2], acc[r * 4 + 3]);
        }
        __syncthreads();

        // --- step2: warp0 factors 16x16 diag block; writes psol + invL ---
        if (tid < 32) {
            const int lane = tid;
            float rw[16];
            if (lane < 16) {
                #pragma unroll
                for (int j = 0; j < 16; ++j)
                    rw[j] = (j <= lane) ? praw[(k0 + lane) * PBS + j] : 0.0f;
            } else {
                #pragma unroll
                for (int j = 0; j < 16; ++j) rw[j] = 0.0f;
            }
            #pragma unroll
            for (int c = 0; c < 16; ++c) {
                float dcc = __shfl_sync(0xffffffffu, rw[c], c);
                float lcc = sqrtf(dcc);
                float inv = 1.0f / lcc;
                if (lane == c) { rw[c] = lcc; invd[c] = inv; }
                else if (lane > c && lane < 16) rw[c] *= inv;
                float vc = rw[c];
                #pragma unroll
                for (int j = c + 1; j < 16; ++j) {
                    float vj = __shfl_sync(0xffffffffu, vc, j);
                    if (lane >= j && lane < 16) rw[j] -= vc * vj;
                }
            }
            if (lane < 16) {
                #pragma unroll
                for (int j = 0; j < 16; ++j)
                    psol[(k0 + lane) * PBS + j] = (j <= lane) ? rw[j] : 0.0f;
            }
            __syncwarp();
            // inv(L11), column `lane`
            if (lane < 16) {
                float x[16];
                #pragma unroll
                for (int r = 0; r < 16; ++r) {
                    float s = (r == lane) ? 1.0f : 0.0f;
                    const int rr = (k0 + r) * PBS;
                    #pragma unroll
                    for (int d = 0; d < r; ++d)
                        s -= psol[rr + d] * x[d];
                    x[r] = s * invd[r];
                    invL[r * 17 + lane] = x[r];
                }
            }
        }
        __syncthreads();

        // --- step3: panel solve, 4 threads per row ---
        const int rem = 112 - k0;
        if (rem > 0 && tid < 4 * rem) {
            const int row = k0 + 16 + (tid >> 2);
            const int p = (tid & 3) * 4;
            float r[16];
            #pragma unroll
            for (int c4 = 0; c4 < 4; ++c4) {
                float4 v = *reinterpret_cast<const float4*>(&praw[row * PBS + c4 * 4]);
                r[c4 * 4 + 0] = v.x; r[c4 * 4 + 1] = v.y;
                r[c4 * 4 + 2] = v.z; r[c4 * 4 + 3] = v.w;
            }
            float o[4];
            #pragma unroll
            for (int cc = 0; cc < 4; ++cc) {
                const int c = p + cc;
                float s = 0.0f;
                #pragma unroll
                for (int d = 0; d < 16; ++d)
                    if (d <= c) s = fmaf(invL[c * 17 + d], r[d], s);
                o[cc] = s;
            }
            *reinterpret_cast<float4*>(&psol[row * PBS + p]) =
                make_float4(o[0], o[1], o[2], o[3]);
        }
        __syncthreads();

        // --- step4: trailing update in regs / retire panel tiles ---
        if (owner) {
            if (tjblk == kb) {
                const int co = jb - k0;
                #pragma unroll
                for (int r = 0; r < 4; ++r) {
                    float4 v = *reinterpret_cast<const float4*>(&psol[(ib + r) * PBS + co]);
                    acc[r * 4 + 0] = v.x; acc[r * 4 + 1] = v.y;
                    acc[r * 4 + 2] = v.z; acc[r * 4 + 3] = v.w;
                }
            } else if (tjblk > kb) {
                #pragma unroll
                for (int q = 0; q < 4; ++q) {
                    float4 li[4], lj[4];
                    #pragma unroll
                    for (int r = 0; r < 4; ++r) {
                        li[r] = *reinterpret_cast<const float4*>(&psol[(ib + r) * PBS + q * 4]);
                        lj[r] = *reinterpret_cast<const float4*>(&psol[(jb + r) * PBS + q * 4]);
                    }
                    #pragma unroll
                    for (int r = 0; r < 4; ++r)
                        #pragma unroll
                        for (int s = 0; s < 4; ++s) {
                            float a = acc[r * 4 + s];
                            a = fmaf(-li[r].x, lj[s].x, a);
                            a = fmaf(-li[r].y, lj[s].y, a);
                            a = fmaf(-li[r].z, lj[s].z, a);
                            a = fmaf(-li[r].w, lj[s].w, a);
                            acc[r * 4 + s] = a;
                        }
                }
            }
        }
    }

    // ---- write chol from registers (lower; zeros above) ----
    if (owner) {
        #pragma unroll
        for (int r = 0; r < 4; ++r) {
            const int i = ib + r;
            float va[4];
            #pragma unroll
            for (int c = 0; c < 4; ++c)
                va[c] = (jb + c <= i) ? acc[r * 4 + c] : 0.0f;
            *reinterpret_cast<float4*>(c_out + i * 128 + jb) =
                make_float4(va[0], va[1], va[2], va[3]);
        }
        if (ti > tj) {
            const float4 z = make_float4(0.0f, 0.0f, 0.0f, 0.0f);
            #pragma unroll
            for (int c = 0; c < 4; ++c)
                *reinterpret_cast<float4*>(c_out + (jb + c) * 128 + ib) = z;
        }
    }
}

extern "C" void kernel_launch(void* const* d_in, const int* in_sizes, int n_in,
                              void* d_out, int out_size)
{
    const float* aug      = (const float*)d_in[0];
    const float* theta    = (const float*)d_in[1];
    const float* scales   = (const float*)d_in[2];
    const float* nug_mean = (const float*)d_in[3];
    const int*   bidx     = (const int*)d_in[4];
    float* out = (float*)d_out;

    const size_t smem_bytes = (size_t)SMEM_FLOATS * sizeof(float);
    cudaFuncSetAttribute(otm_fused_kernel,
                         cudaFuncAttributeMaxDynamicSharedMemorySize,
                         (int)smem_bytes);

    otm_fused_kernel<<<N_LOC, NT, smem_bytes>>>(aug, theta, scales, nug_mean,
                                                bidx, out);
}

// round 9
// speedup vs baseline: 1.3694x; 1.3694x over previous
#include <cuda_runtime.h>
#include <math.h>

#define N_LOC 4096
#define N_REP 128
#define M_NBR 48

// packed lower-triangle row offset (rows padded to multiples of 4)
__device__ __forceinline__ int aoff(int i) {
    int q = i >> 2;
    return 4 * (q + 1) * (2 * q + (i & 3));
}

__device__ __forceinline__ void tridec(int t, int& row, int& col) {
    int r = (int)((sqrtf(8.0f * (float)t + 1.0f) - 1.0f) * 0.5f);
    while ((r + 1) * (r + 2) / 2 <= t) ++r;
    while (r * (r + 1) / 2 > t) --r;
    row = r;
    col = t - r * (r + 1) / 2;
}

// ===================== Kernel 1: gram + Matern epilogue -> g =====================
__global__ __launch_bounds__(512, 3)
void gram_kernel(const float* __restrict__ aug,
                 const float* __restrict__ theta,
                 const float* __restrict__ scales,
                 const float* __restrict__ nug_mean,
                 const int* __restrict__ batch_idx,
                 float* __restrict__ out)
{
    const int N = blockIdx.x;
    const int tid = threadIdx.x;
    float* g_out = out + (size_t)N * 16384;

    if (batch_idx[N] == 0) {
        for (int idx = tid; idx < 16384; idx += 512)
            g_out[idx] = ((idx >> 7) == (idx & 127)) ? 1.0f : 0.0f;
        return;
    }

    __shared__ float xs[M_NBR * 128];
    __shared__ float diag[128];
    __shared__ float scalm[M_NBR];

    const float t2 = theta[2];
    const float t3 = theta[3];
    const float t4 = theta[4];
    const float t5 = theta[5];
    const float ls = expf(t5) * 1.7320508075688772f;
    const float inv_ls2 = 1.0f / (ls * ls);
    const float sig2 = expf(2.0f * (logf(scales[N]) * t4 + t3));
    const float inv_nug = 1.0f / nug_mean[N];

    if (tid < M_NBR)
        scalm[tid] = expf(-0.5f * (float)(tid + 1) * expf(t2));
    __syncthreads();

    {
        const float* base = aug + (size_t)N * (M_NBR + 1) + 1;
        for (int idx = tid; idx < N_REP * M_NBR; idx += 512) {
            int i = idx / M_NBR;
            int m = idx - i * M_NBR;
            float v = base[(size_t)i * ((size_t)N_LOC * (M_NBR + 1)) + m];
            if (v != v) v = 0.0f;
            xs[m * 128 + i] = v * scalm[m];
        }
    }
    __syncthreads();

    if (tid < N_REP) {
        float d = 0.0f;
        #pragma unroll
        for (int m = 0; m < M_NBR; ++m) {
            float v = xs[m * 128 + tid];
            d = fmaf(v, v, d);
        }
        diag[tid] = d;
    }
    __syncthreads();

    for (int t = tid; t < 528; t += 512) {
        int ti, tj;
        tridec(t, ti, tj);
        const int ib = ti * 4, jb = tj * 4;

        float acc[16];
        #pragma unroll
        for (int k = 0; k < 16; ++k) acc[k] = 0.0f;

        #pragma unroll 4
        for (int m = 0; m < M_NBR; ++m) {
            const float* row = xs + m * 128;
            float4 a = *reinterpret_cast<const float4*>(row + ib);
            float4 b = *reinterpret_cast<const float4*>(row + jb);
            float av[4] = {a.x, a.y, a.z, a.w};
            float bv[4] = {b.x, b.y, b.z, b.w};
            #pragma unroll
            for (int r = 0; r < 4; ++r)
                #pragma unroll
                for (int c = 0; c < 4; ++c)
                    acc[r * 4 + c] = fmaf(av[r], bv[c], acc[r * 4 + c]);
        }

        float di[4], dj[4];
        #pragma unroll
        for (int r = 0; r < 4; ++r) di[r] = diag[ib + r];
        #pragma unroll
        for (int c = 0; c < 4; ++c) dj[c] = diag[jb + c];

        #pragma unroll
        for (int r = 0; r < 4; ++r)
            #pragma unroll
            for (int c = 0; c < 4; ++c) {
                float G = acc[r * 4 + c];
                float sq = fmaxf((di[r] + dj[c] - 2.0f * G) * inv_ls2, 0.0f);
                float s3 = 1.7320508075688772f * sq * __frsqrt_rn(fmaxf(sq, 1e-30f));
                float mat = (1.0f + s3) * __expf(-s3);
                acc[r * 4 + c] = (G + sig2 * mat) * inv_nug
                               + ((ib + r == jb + c) ? 1.0f : 0.0f);
            }

        #pragma unroll
        for (int r = 0; r < 4; ++r)
            *reinterpret_cast<float4*>(g_out + (ib + r) * 128 + jb) =
                make_float4(acc[r * 4], acc[r * 4 + 1], acc[r * 4 + 2], acc[r * 4 + 3]);
        if (ti > tj) {
            #pragma unroll
            for (int c = 0; c < 4; ++c)
                *reinterpret_cast<float4*>(g_out + (jb + c) * 128 + ib) =
                    make_float4(acc[c], acc[4 + c], acc[8 + c], acc[12 + c]);
        }
    }
}

// ===================== Kernel 2: batched Cholesky (reads g, writes chol) ========
__global__ __launch_bounds__(128, 6)
void chol_kernel(float* __restrict__ out)
{
    const int N = blockIdx.x;
    const int tid = threadIdx.x;
    const float* g_in = out + (size_t)N * 16384;
    float* c_out = out + (size_t)N_LOC * 16384 + (size_t)N * 16384;

    __shared__ float Apk[8448];       // packed lower triangle
    __shared__ float invd[16];
    __shared__ float invL[16 * 17];

    // ---- load lower triangle of g into packed smem; thread = row ----
    {
        const int i = tid;
        const int ro = aoff(i);
        const int nch = (i >> 2) + 1;
        const float* grow = g_in + i * 128;
        for (int c4 = 0; c4 < nch; ++c4)
            *reinterpret_cast<float4*>(&Apk[ro + c4 * 4]) =
                *reinterpret_cast<const float4*>(grow + c4 * 4);
    }
    __syncthreads();

    // ---- blocked Cholesky, NB=16 ----
    #pragma unroll 1
    for (int kb = 0; kb < 8; ++kb) {
        const int k0 = kb * 16;

        // (a) warp0: factor 16x16 diag block
        if (tid < 32) {
            const int lane = tid;
            float rw[16];
            const int ro = (lane < 16) ? (aoff(k0 + lane) + k0) : 0;
            if (lane < 16) {
                #pragma unroll
                for (int j = 0; j < 16; ++j)
                    rw[j] = (j <= lane) ? Apk[ro + j] : 0.0f;
            } else {
                #pragma unroll
                for (int j = 0; j < 16; ++j) rw[j] = 0.0f;
            }
            #pragma unroll
            for (int c = 0; c < 16; ++c) {
                float dcc = __shfl_sync(0xffffffffu, rw[c], c);
                float lcc = sqrtf(dcc);
                float inv = 1.0f / lcc;
                if (lane == c) { rw[c] = lcc; invd[c] = inv; }
                else if (lane > c && lane < 16) rw[c] *= inv;
                float vc = rw[c];
                #pragma unroll
                for (int j = c + 1; j < 16; ++j) {
                    float vj = __shfl_sync(0xffffffffu, vc, j);
                    if (lane >= j && lane < 16) rw[j] -= vc * vj;
                }
            }
            if (lane < 16) {
                #pragma unroll
                for (int j = 0; j < 16; ++j)
                    if (j <= lane) Apk[ro + j] = rw[j];
            }
            __syncwarp();

            // (a2) inv(L11) column `lane`
            if (lane < 16) {
                float x[16];
                #pragma unroll
                for (int r = 0; r < 16; ++r) {
                    float s = (r == lane) ? 1.0f : 0.0f;
                    const int rr = aoff(k0 + r) + k0;
                    #pragma unroll
                    for (int d = 0; d < r; ++d)
                        s -= Apk[rr + d] * x[d];
                    x[r] = s * invd[r];
                    invL[r * 17 + lane] = x[r];
                }
            }
        }
        __syncthreads();

        const int rem = 112 - k0;
        if (rem > 0) {
            // (b) panel solve, 1 thread per row
            if (tid < rem) {
                const int i = k0 + 16 + tid;
                const int ro = aoff(i) + k0;
                float r[16];
                #pragma unroll
                for (int c4 = 0; c4 < 4; ++c4) {
                    float4 v = *reinterpret_cast<const float4*>(&Apk[ro + c4 * 4]);
                    r[c4 * 4 + 0] = v.x; r[c4 * 4 + 1] = v.y;
                    r[c4 * 4 + 2] = v.z; r[c4 * 4 + 3] = v.w;
                }
                #pragma unroll
                for (int c = 0; c < 16; ++c) {
                    float s = 0.0f;
                    #pragma unroll
                    for (int d = 0; d <= c; ++d)
                        s = fmaf(invL[c * 17 + d], r[d], s);
                    Apk[ro + c] = s;
                }
            }
            __syncthreads();

            // (c) trailing rank-16 update: 4x4 tiles over lower triangle
            const int ntr = rem >> 2;
            const int ntiles = ntr * (ntr + 1) / 2;
            for (int t = tid; t < ntiles; t += 128) {
                int ti, tj;
                tridec(t, ti, tj);
                const int ib = k0 + 16 + ti * 4;
                const int jb = k0 + 16 + tj * 4;
                int roi[4], roj[4];
                #pragma unroll
                for (int r = 0; r < 4; ++r) {
                    roi[r] = aoff(ib + r) + k0;
                    roj[r] = aoff(jb + r) + k0;
                }
                float acc[16];
                #pragma unroll
                for (int k = 0; k < 16; ++k) acc[k] = 0.0f;

                #pragma unroll
                for (int c2 = 0; c2 < 8; ++c2) {
                    float2 li[4], lj[4];
                    #pragma unroll
                    for (int r = 0; r < 4; ++r) {
                        li[r] = *reinterpret_cast<const float2*>(&Apk[roi[r] + c2 * 2]);
                        lj[r] = *reinterpret_cast<const float2*>(&Apk[roj[r] + c2 * 2]);
                    }
                    #pragma unroll
                    for (int r = 0; r < 4; ++r)
                        #pragma unroll
                        for (int s = 0; s < 4; ++s) {
                            acc[r * 4 + s] = fmaf(li[r].x, lj[s].x, acc[r * 4 + s]);
                            acc[r * 4 + s] = fmaf(li[r].y, lj[s].y, acc[r * 4 + s]);
                        }
                }
                #pragma unroll
                for (int r = 0; r < 4; ++r) {
                    const int i = ib + r;
                    const int ro = aoff(i);
                    #pragma unroll
                    for (int s = 0; s < 4; ++s) {
                        const int j = jb + s;
                        if (j <= i) Apk[ro + j] -= acc[r * 4 + s];
                    }
                }
            }
        }
        __syncthreads();
    }

    // ---- write chol: full row per thread (lower values, zeros above) ----
    {
        const int i = tid;
        const int ro = aoff(i);
        float* crow = c_out + i * 128;
        for (int c4 = 0; c4 < 32; ++c4) {
            const int j0 = c4 * 4;
            float va[4];
            #pragma unroll
            for (int c = 0; c < 4; ++c)
                va[c] = (j0 + c <= i) ? Apk[ro + j0 + c] : 0.0f;
            *reinterpret_cast<float4*>(crow + j0) =
                make_float4(va[0], va[1], va[2], va[3]);
        }
    }
}

extern "C" void kernel_launch(void* const* d_in, const int* in_sizes, int n_in,
                              void* d_out, int out_size)
{
    const float* aug      = (const float*)d_in[0];
    const float* theta    = (const float*)d_in[1];
    const float* scales   = (const float*)d_in[2];
    const float* nug_mean = (const float*)d_in[3];
    const int*   bidx     = (const int*)d_in[4];
    float* out = (float*)d_out;

    gram_kernel<<<N_LOC, 512>>>(aug, theta, scales, nug_mean, bidx, out);
    chol_kernel<<<N_LOC, 128>>>(out);
}

// round 10
// speedup vs baseline: 1.4599x; 1.0661x over previous
#include <cuda_runtime.h>
#include <math.h>

#define N_LOC 4096
#define N_REP 128
#define M_NBR 48

// packed lower-triangle row offset (rows padded to multiples of 4)
__device__ __forceinline__ int aoff(int i) {
    int q = i >> 2;
    return 4 * (q + 1) * (2 * q + (i & 3));
}

__device__ __forceinline__ void tridec(int t, int& row, int& col) {
    int r = (int)((sqrtf(8.0f * (float)t + 1.0f) - 1.0f) * 0.5f);
    while ((r + 1) * (r + 2) / 2 <= t) ++r;
    while (r * (r + 1) / 2 > t) --r;
    row = r;
    col = t - r * (r + 1) / 2;
}

// ===================== Kernel 1: gram + Matern epilogue -> g =====================
__global__ __launch_bounds__(512, 3)
void gram_kernel(const float* __restrict__ aug,
                 const float* __restrict__ theta,
                 const float* __restrict__ scales,
                 const float* __restrict__ nug_mean,
                 const int* __restrict__ batch_idx,
                 float* __restrict__ out)
{
    const int N = blockIdx.x;
    const int tid = threadIdx.x;
    float* g_out = out + (size_t)N * 16384;

    if (batch_idx[N] == 0) {
        for (int idx = tid; idx < 16384; idx += 512)
            g_out[idx] = ((idx >> 7) == (idx & 127)) ? 1.0f : 0.0f;
        return;
    }

    __shared__ float xs[M_NBR * 128];
    __shared__ float diag[128];
    __shared__ float scalm[M_NBR];

    const float t2 = theta[2];
    const float t3 = theta[3];
    const float t4 = theta[4];
    const float t5 = theta[5];
    const float ls = expf(t5) * 1.7320508075688772f;
    const float inv_ls2 = 1.0f / (ls * ls);
    const float sig2 = expf(2.0f * (logf(scales[N]) * t4 + t3));
    const float inv_nug = 1.0f / nug_mean[N];

    if (tid < M_NBR)
        scalm[tid] = expf(-0.5f * (float)(tid + 1) * expf(t2));
    __syncthreads();

    {
        const float* base = aug + (size_t)N * (M_NBR + 1) + 1;
        for (int idx = tid; idx < N_REP * M_NBR; idx += 512) {
            int i = idx / M_NBR;
            int m = idx - i * M_NBR;
            float v = base[(size_t)i * ((size_t)N_LOC * (M_NBR + 1)) + m];
            if (v != v) v = 0.0f;
            xs[m * 128 + i] = v * scalm[m];
        }
    }
    __syncthreads();

    if (tid < N_REP) {
        float d = 0.0f;
        #pragma unroll
        for (int m = 0; m < M_NBR; ++m) {
            float v = xs[m * 128 + tid];
            d = fmaf(v, v, d);
        }
        diag[tid] = d;
    }
    __syncthreads();

    for (int t = tid; t < 528; t += 512) {
        int ti, tj;
        tridec(t, ti, tj);
        const int ib = ti * 4, jb = tj * 4;

        float acc[16];
        #pragma unroll
        for (int k = 0; k < 16; ++k) acc[k] = 0.0f;

        #pragma unroll 4
        for (int m = 0; m < M_NBR; ++m) {
            const float* row = xs + m * 128;
            float4 a = *reinterpret_cast<const float4*>(row + ib);
            float4 b = *reinterpret_cast<const float4*>(row + jb);
            float av[4] = {a.x, a.y, a.z, a.w};
            float bv[4] = {b.x, b.y, b.z, b.w};
            #pragma unroll
            for (int r = 0; r < 4; ++r)
                #pragma unroll
                for (int c = 0; c < 4; ++c)
                    acc[r * 4 + c] = fmaf(av[r], bv[c], acc[r * 4 + c]);
        }

        float di[4], dj[4];
        #pragma unroll
        for (int r = 0; r < 4; ++r) di[r] = diag[ib + r];
        #pragma unroll
        for (int c = 0; c < 4; ++c) dj[c] = diag[jb + c];

        #pragma unroll
        for (int r = 0; r < 4; ++r)
            #pragma unroll
            for (int c = 0; c < 4; ++c) {
                float G = acc[r * 4 + c];
                float sq = fmaxf((di[r] + dj[c] - 2.0f * G) * inv_ls2, 0.0f);
                float s3 = 1.7320508075688772f * sq * __frsqrt_rn(fmaxf(sq, 1e-30f));
                float mat = (1.0f + s3) * __expf(-s3);
                acc[r * 4 + c] = (G + sig2 * mat) * inv_nug
                               + ((ib + r == jb + c) ? 1.0f : 0.0f);
            }

        #pragma unroll
        for (int r = 0; r < 4; ++r)
            *reinterpret_cast<float4*>(g_out + (ib + r) * 128 + jb) =
                make_float4(acc[r * 4], acc[r * 4 + 1], acc[r * 4 + 2], acc[r * 4 + 3]);
        if (ti > tj) {
            #pragma unroll
            for (int c = 0; c < 4; ++c)
                *reinterpret_cast<float4*>(g_out + (jb + c) * 128 + ib) =
                    make_float4(acc[c], acc[4 + c], acc[8 + c], acc[12 + c]);
        }
    }
}

// ===================== Kernel 2: batched Cholesky ===============================

// warp-cooperative rank-16 update of one 4-row block.
// lanes = 4-col groups over [c_lo, ib+4); reads psolT (transposed panel).
__device__ __forceinline__ void rb_update(float* __restrict__ Apk,
                                          const float* __restrict__ psolT,
                                          int ib, int c_lo, int lane)
{
    const int ng = (ib + 4 - c_lo) >> 2;
    if (lane >= ng) return;
    const int jb = c_lo + lane * 4;

    float acc[16];
    #pragma unroll
    for (int k = 0; k < 16; ++k) acc[k] = 0.0f;

    #pragma unroll
    for (int d = 0; d < 16; ++d) {
        float4 bc = *reinterpret_cast<const float4*>(&psolT[d * 132 + ib]);  // broadcast
        float4 lv = *reinterpret_cast<const float4*>(&psolT[d * 132 + jb]);  // coalesced
        float b[4] = {bc.x, bc.y, bc.z, bc.w};
        float v[4] = {lv.x, lv.y, lv.z, lv.w};
        #pragma unroll
        for (int r = 0; r < 4; ++r)
            #pragma unroll
            for (int s = 0; s < 4; ++s)
                acc[r * 4 + s] = fmaf(b[r], v[s], acc[r * 4 + s]);
    }

    #pragma unroll
    for (int r = 0; r < 4; ++r) {
        const int i = ib + r;
        const int ro = aoff(i);
        if (jb + 3 <= i) {
            float4 a = *reinterpret_cast<float4*>(&Apk[ro + jb]);
            a.x -= acc[r * 4 + 0];
            a.y -= acc[r * 4 + 1];
            a.z -= acc[r * 4 + 2];
            a.w -= acc[r * 4 + 3];
            *reinterpret_cast<float4*>(&Apk[ro + jb]) = a;
        } else {
            #pragma unroll
            for (int s = 0; s < 4; ++s) {
                const int j = jb + s;
                if (j <= i) Apk[ro + j] -= acc[r * 4 + s];
            }
        }
    }
}

// warp0: factor 16x16 diag block at k0 (in Apk), produce invd + invL.
__device__ __forceinline__ void diag_factor(float* __restrict__ Apk,
                                            float* __restrict__ invd,
                                            float* __restrict__ invL,
                                            int k0, int lane)
{
    float rw[16];
    const int ro = (lane < 16) ? (aoff(k0 + lane) + k0) : 0;
    if (lane < 16) {
        #pragma unroll
        for (int j = 0; j < 16; ++j)
            rw[j] = (j <= lane) ? Apk[ro + j] : 0.0f;
    } else {
        #pragma unroll
        for (int j = 0; j < 16; ++j) rw[j] = 0.0f;
    }
    #pragma unroll
    for (int c = 0; c < 16; ++c) {
        float dcc = __shfl_sync(0xffffffffu, rw[c], c);
        float lcc = sqrtf(dcc);
        float inv = 1.0f / lcc;
        if (lane == c) { rw[c] = lcc; invd[c] = inv; }
        else if (lane > c && lane < 16) rw[c] *= inv;
        float vc = rw[c];
        #pragma unroll
        for (int j = c + 1; j < 16; ++j) {
            float vj = __shfl_sync(0xffffffffu, vc, j);
            if (lane >= j && lane < 16) rw[j] -= vc * vj;
        }
    }
    if (lane < 16) {
        #pragma unroll
        for (int j = 0; j < 16; ++j)
            if (j <= lane) Apk[ro + j] = rw[j];
    }
    __syncwarp();
    // inv(L11) column `lane`
    if (lane < 16) {
        float x[16];
        #pragma unroll
        for (int r = 0; r < 16; ++r) {
            float s = (r == lane) ? 1.0f : 0.0f;
            const int rr = aoff(k0 + r) + k0;
            #pragma unroll
            for (int d = 0; d < r; ++d)
                s -= Apk[rr + d] * x[d];
            x[r] = s * invd[r];
            invL[r * 17 + lane] = x[r];
        }
    }
}

__global__ __launch_bounds__(128, 5)
void chol_kernel(float* __restrict__ out)
{
    const int N = blockIdx.x;
    const int tid = threadIdx.x;
    const int wrp = tid >> 5;
    const int lane = tid & 31;
    const float* g_in = out + (size_t)N * 16384;
    float* c_out = out + (size_t)N_LOC * 16384 + (size_t)N * 16384;

    __shared__ float Apk[8448];       // packed lower triangle
    __shared__ float psolT[16 * 132]; // transposed solved panel: [d][row]
    __shared__ float invd[16];
    __shared__ float invL[16 * 17];

    // ---- load lower triangle of g into packed smem; thread = row ----
    {
        const int i = tid;
        const int ro = aoff(i);
        const int nch = (i >> 2) + 1;
        const float* grow = g_in + i * 128;
        for (int c4 = 0; c4 < nch; ++c4)
            *reinterpret_cast<float4*>(&Apk[ro + c4 * 4]) =
                *reinterpret_cast<const float4*>(grow + c4 * 4);
    }
    __syncthreads();

    // ---- kb = 0: factor diag block 0 ----
    if (wrp == 0) diag_factor(Apk, invd, invL, 0, lane);
    __syncthreads();

    // ---- panel solve 0 (rows 16..127) ----
    if (tid < 112) {
        const int i = 16 + tid;
        const int ro = aoff(i);
        float r[16];
        #pragma unroll
        for (int c4 = 0; c4 < 4; ++c4) {
            float4 v = *reinterpret_cast<const float4*>(&Apk[ro + c4 * 4]);
            r[c4 * 4 + 0] = v.x; r[c4 * 4 + 1] = v.y;
            r[c4 * 4 + 2] = v.z; r[c4 * 4 + 3] = v.w;
        }
        #pragma unroll
        for (int c = 0; c < 16; ++c) {
            float s = 0.0f;
            #pragma unroll
            for (int d = 0; d <= c; ++d)
                s = fmaf(invL[c * 17 + d], r[d], s);
            Apk[ro + c] = s;
            psolT[c * 132 + i] = s;
        }
    }
    __syncthreads();

    // ---- kb = 1..7: pipelined: c1 (diag-block update), c2 (factor || trailing), panel
    #pragma unroll 1
    for (int kb = 1; kb < 8; ++kb) {
        const int k0 = kb * 16;

        // c1: update diag block kb with latest panel; warp w -> row-block k0+4w
        rb_update(Apk, psolT, k0 + 4 * wrp, k0, lane);
        __syncthreads();

        // c2: warp0 factors diag kb; warps 1-3 update remaining trailing rows
        if (wrp == 0) {
            diag_factor(Apk, invd, invL, k0, lane);
        } else {
            const int nb = (112 - k0) >> 2;
            for (int bi = wrp - 1; bi < nb; bi += 3)
                rb_update(Apk, psolT, k0 + 16 + bi * 4, k0, lane);
        }
        __syncthreads();

        // panel solve kb (rows k0+16..127)
        const int rem = 112 - k0;
        if (rem > 0) {
            if (tid < rem) {
                const int i = k0 + 16 + tid;
                const int ro = aoff(i) + k0;
                float r[16];
                #pragma unroll
                for (int c4 = 0; c4 < 4; ++c4) {
                    float4 v = *reinterpret_cast<const float4*>(&Apk[ro + c4 * 4]);
                    r[c4 * 4 + 0] = v.x; r[c4 * 4 + 1] = v.y;
                    r[c4 * 4 + 2] = v.z; r[c4 * 4 + 3] = v.w;
                }
                #pragma unroll
                for (int c = 0; c < 16; ++c) {
                    float s = 0.0f;
                    #pragma unroll
                    for (int d = 0; d <= c; ++d)
                        s = fmaf(invL[c * 17 + d], r[d], s);
                    Apk[ro + c] = s;
                    psolT[c * 132 + i] = s;
                }
            }
            __syncthreads();
        }
    }

    // ---- write chol: full row per thread (lower values, zeros above) ----
    {
        const int i = tid;
        const int ro = aoff(i);
        float* crow = c_out + i * 128;
        for (int c4 = 0; c4 < 32; ++c4) {
            const int j0 = c4 * 4;
            float va[4];
            #pragma unroll
            for (int c = 0; c < 4; ++c)
                va[c] = (j0 + c <= i) ? Apk[ro + j0 + c] : 0.0f;
            *reinterpret_cast<float4*>(crow + j0) =
                make_float4(va[0], va[1], va[2], va[3]);
        }
    }
}

extern "C" void kernel_launch(void* const* d_in, const int* in_sizes, int n_in,
                              void* d_out, int out_size)
{
    const float* aug      = (const float*)d_in[0];
    const float* theta    = (const float*)d_in[1];
    const float* scales   = (const float*)d_in[2];
    const float* nug_mean = (const float*)d_in[3];
    const int*   bidx     = (const int*)d_in[4];
    float* out = (float*)d_out;

    gram_kernel<<<N_LOC, 512>>>(aug, theta, scales, nug_mean, bidx, out);
    chol_kernel<<<N_LOC, 128>>>(out);
}

// round 11
// speedup vs baseline: 1.4621x; 1.0015x over previous
#include <cuda_runtime.h>
#include <math.h>

#define N_LOC 4096
#define N_REP 128
#define M_NBR 48

// packed lower-triangle row offset (rows padded to multiples of 4)
__device__ __forceinline__ int aoff(int i) {
    int q = i >> 2;
    return 4 * (q + 1) * (2 * q + (i & 3));
}

__device__ __forceinline__ void tridec(int t, int& row, int& col) {
    int r = (int)((sqrtf(8.0f * (float)t + 1.0f) - 1.0f) * 0.5f);
    while ((r + 1) * (r + 2) / 2 <= t) ++r;
    while (r * (r + 1) / 2 > t) --r;
    row = r;
    col = t - r * (r + 1) / 2;
}

// ===================== Kernel 1: gram + Matern epilogue -> g =====================
__global__ __launch_bounds__(512, 3)
void gram_kernel(const float* __restrict__ aug,
                 const float* __restrict__ theta,
                 const float* __restrict__ scales,
                 const float* __restrict__ nug_mean,
                 const int* __restrict__ batch_idx,
                 float* __restrict__ out)
{
    const int N = blockIdx.x;
    const int tid = threadIdx.x;
    float* g_out = out + (size_t)N * 16384;

    if (batch_idx[N] == 0) {
        for (int idx = tid; idx < 16384; idx += 512)
            g_out[idx] = ((idx >> 7) == (idx & 127)) ? 1.0f : 0.0f;
        return;
    }

    __shared__ float xs[M_NBR * 128];
    __shared__ float diag[128];
    __shared__ float scalm[M_NBR];

    const float t2 = theta[2];
    const float t3 = theta[3];
    const float t4 = theta[4];
    const float t5 = theta[5];
    const float ls = expf(t5) * 1.7320508075688772f;
    const float inv_ls2 = 1.0f / (ls * ls);
    const float sig2 = expf(2.0f * (logf(scales[N]) * t4 + t3));
    const float inv_nug = 1.0f / nug_mean[N];

    if (tid < M_NBR)
        scalm[tid] = expf(-0.5f * (float)(tid + 1) * expf(t2));
    __syncthreads();

    {
        const float* base = aug + (size_t)N * (M_NBR + 1) + 1;
        for (int idx = tid; idx < N_REP * M_NBR; idx += 512) {
            int i = idx / M_NBR;
            int m = idx - i * M_NBR;
            float v = base[(size_t)i * ((size_t)N_LOC * (M_NBR + 1)) + m];
            if (v != v) v = 0.0f;
            xs[m * 128 + i] = v * scalm[m];
        }
    }
    __syncthreads();

    if (tid < N_REP) {
        float d = 0.0f;
        #pragma unroll
        for (int m = 0; m < M_NBR; ++m) {
            float v = xs[m * 128 + tid];
            d = fmaf(v, v, d);
        }
        diag[tid] = d;
    }
    __syncthreads();

    for (int t = tid; t < 528; t += 512) {
        int ti, tj;
        tridec(t, ti, tj);
        const int ib = ti * 4, jb = tj * 4;

        float acc[16];
        #pragma unroll
        for (int k = 0; k < 16; ++k) acc[k] = 0.0f;

        #pragma unroll 4
        for (int m = 0; m < M_NBR; ++m) {
            const float* row = xs + m * 128;
            float4 a = *reinterpret_cast<const float4*>(row + ib);
            float4 b = *reinterpret_cast<const float4*>(row + jb);
            float av[4] = {a.x, a.y, a.z, a.w};
            float bv[4] = {b.x, b.y, b.z, b.w};
            #pragma unroll
            for (int r = 0; r < 4; ++r)
                #pragma unroll
                for (int c = 0; c < 4; ++c)
                    acc[r * 4 + c] = fmaf(av[r], bv[c], acc[r * 4 + c]);
        }

        float di[4], dj[4];
        #pragma unroll
        for (int r = 0; r < 4; ++r) di[r] = diag[ib + r];
        #pragma unroll
        for (int c = 0; c < 4; ++c) dj[c] = diag[jb + c];

        #pragma unroll
        for (int r = 0; r < 4; ++r)
            #pragma unroll
            for (int c = 0; c < 4; ++c) {
                float G = acc[r * 4 + c];
                float sq = fmaxf((di[r] + dj[c] - 2.0f * G) * inv_ls2, 0.0f);
                float s3 = 1.7320508075688772f * sq * __frsqrt_rn(fmaxf(sq, 1e-30f));
                float mat = (1.0f + s3) * __expf(-s3);
                acc[r * 4 + c] = (G + sig2 * mat) * inv_nug
                               + ((ib + r == jb + c) ? 1.0f : 0.0f);
            }

        #pragma unroll
        for (int r = 0; r < 4; ++r)
            *reinterpret_cast<float4*>(g_out + (ib + r) * 128 + jb) =
                make_float4(acc[r * 4], acc[r * 4 + 1], acc[r * 4 + 2], acc[r * 4 + 3]);
        if (ti > tj) {
            #pragma unroll
            for (int c = 0; c < 4; ++c)
                *reinterpret_cast<float4*>(g_out + (jb + c) * 128 + ib) =
                    make_float4(acc[c], acc[4 + c], acc[8 + c], acc[12 + c]);
        }
    }
}

// ===================== Kernel 2: batched Cholesky ===============================

// per-thread rank-16 update of 4x4 tile (ib,jb) from transposed panel psolT
__device__ __forceinline__ void tile_update(float* __restrict__ Apk,
                                            const float* __restrict__ psolT,
                                            int ib, int jb)
{
    float acc[16];
    #pragma unroll
    for (int k = 0; k < 16; ++k) acc[k] = 0.0f;

    #pragma unroll
    for (int d = 0; d < 16; ++d) {
        float4 av = *reinterpret_cast<const float4*>(&psolT[d * 132 + ib]);
        float4 bv = *reinterpret_cast<const float4*>(&psolT[d * 132 + jb]);
        float a[4] = {av.x, av.y, av.z, av.w};
        float b[4] = {bv.x, bv.y, bv.z, bv.w};
        #pragma unroll
        for (int r = 0; r < 4; ++r)
            #pragma unroll
            for (int s = 0; s < 4; ++s)
                acc[r * 4 + s] = fmaf(a[r], b[s], acc[r * 4 + s]);
    }

    #pragma unroll
    for (int r = 0; r < 4; ++r) {
        const int i = ib + r;
        const int ro = aoff(i);
        if (jb + 3 <= i) {
            float4 a = *reinterpret_cast<float4*>(&Apk[ro + jb]);
            a.x -= acc[r * 4 + 0];
            a.y -= acc[r * 4 + 1];
            a.z -= acc[r * 4 + 2];
            a.w -= acc[r * 4 + 3];
            *reinterpret_cast<float4*>(&Apk[ro + jb]) = a;
        } else {
            #pragma unroll
            for (int s = 0; s < 4; ++s) {
                const int j = jb + s;
                if (j <= i) Apk[ro + j] -= acc[r * 4 + s];
            }
        }
    }
}

// warp0: factor 16x16 diag block at k0 (in Apk), produce invd + invL.
__device__ __forceinline__ void diag_factor(float* __restrict__ Apk,
                                            float* __restrict__ invd,
                                            float* __restrict__ invL,
                                            int k0, int lane)
{
    float rw[16];
    const int ro = (lane < 16) ? (aoff(k0 + lane) + k0) : 0;
    if (lane < 16) {
        #pragma unroll
        for (int j = 0; j < 16; ++j)
            rw[j] = (j <= lane) ? Apk[ro + j] : 0.0f;
    } else {
        #pragma unroll
        for (int j = 0; j < 16; ++j) rw[j] = 0.0f;
    }
    #pragma unroll
    for (int c = 0; c < 16; ++c) {
        float dcc = __shfl_sync(0xffffffffu, rw[c], c);
        float lcc = sqrtf(dcc);
        float inv = 1.0f / lcc;
        if (lane == c) { rw[c] = lcc; invd[c] = inv; }
        else if (lane > c && lane < 16) rw[c] *= inv;
        float vc = rw[c];
        #pragma unroll
        for (int j = c + 1; j < 16; ++j) {
            float vj = __shfl_sync(0xffffffffu, vc, j);
            if (lane >= j && lane < 16) rw[j] -= vc * vj;
        }
    }
    if (lane < 16) {
        #pragma unroll
        for (int j = 0; j < 16; ++j)
            if (j <= lane) Apk[ro + j] = rw[j];
    }
    __syncwarp();
    // inv(L11) column `lane`
    if (lane < 16) {
        float x[16];
        #pragma unroll
        for (int r = 0; r < 16; ++r) {
            float s = (r == lane) ? 1.0f : 0.0f;
            const int rr = aoff(k0 + r) + k0;
            #pragma unroll
            for (int d = 0; d < r; ++d)
                s -= Apk[rr + d] * x[d];
            x[r] = s * invd[r];
            invL[r * 17 + lane] = x[r];
        }
    }
}

__global__ __launch_bounds__(128, 5)
void chol_kernel(float* __restrict__ out)
{
    const int N = blockIdx.x;
    const int tid = threadIdx.x;
    const int wrp = tid >> 5;
    const int lane = tid & 31;
    const float* g_in = out + (size_t)N * 16384;
    float* c_out = out + (size_t)N_LOC * 16384 + (size_t)N * 16384;

    __shared__ float Apk[8448];       // packed lower triangle
    __shared__ float psolT[16 * 132]; // transposed solved panel: [d][row]
    __shared__ float invd[16];
    __shared__ float invL[16 * 17];

    // ---- load lower triangle of g into packed smem; thread = row ----
    {
        const int i = tid;
        const int ro = aoff(i);
        const int nch = (i >> 2) + 1;
        const float* grow = g_in + i * 128;
        for (int c4 = 0; c4 < nch; ++c4)
            *reinterpret_cast<float4*>(&Apk[ro + c4 * 4]) =
                *reinterpret_cast<const float4*>(grow + c4 * 4);
    }
    __syncthreads();

    // ---- kb = 0: factor diag block 0 ----
    if (wrp == 0) diag_factor(Apk, invd, invL, 0, lane);
    __syncthreads();

    // ---- panel solve 0 (rows 16..127) ----
    if (tid < 112) {
        const int i = 16 + tid;
        const int ro = aoff(i);
        float r[16];
        #pragma unroll
        for (int c4 = 0; c4 < 4; ++c4) {
            float4 v = *reinterpret_cast<const float4*>(&Apk[ro + c4 * 4]);
            r[c4 * 4 + 0] = v.x; r[c4 * 4 + 1] = v.y;
            r[c4 * 4 + 2] = v.z; r[c4 * 4 + 3] = v.w;
        }
        #pragma unroll
        for (int c = 0; c < 16; ++c) {
            float s = 0.0f;
            #pragma unroll
            for (int d = 0; d <= c; ++d)
                s = fmaf(invL[c * 17 + d], r[d], s);
            Apk[ro + c] = s;
            psolT[c * 132 + i] = s;
        }
    }
    __syncthreads();

    // ---- kb = 1..7 pipelined ----
    #pragma unroll 1
    for (int kb = 1; kb < 8; ++kb) {
        const int k0 = kb * 16;
        const int rem = 112 - k0;

        // c1: update diag block kb (10 tiles) + panel columns (rows>=k0+16,
        //     cols k0..k0+15, (rem/4)*4 tiles) using panel kb-1 in psolT
        {
            const int nbp = (rem >> 2) << 2;
            for (int t = tid; t < 10 + nbp; t += 128) {
                int ib, jb;
                if (t < 10) {
                    int ti, tj;
                    tridec(t, ti, tj);
                    ib = k0 + ti * 4;
                    jb = k0 + tj * 4;
                } else {
                    const int idx = t - 10;
                    ib = k0 + 16 + (idx >> 2) * 4;
                    jb = k0 + (idx & 3) * 4;
                }
                tile_update(Apk, psolT, ib, jb);
            }
        }
        __syncthreads();

        // c2: warp0 factors diag kb || warps1-3 update trailing triangle
        if (wrp == 0) {
            diag_factor(Apk, invd, invL, k0, lane);
        } else if (rem > 0) {
            const int ntr = rem >> 2;
            const int ntiles = ntr * (ntr + 1) / 2;
            for (int t = tid - 32; t < ntiles; t += 96) {
                int ti, tj;
                tridec(t, ti, tj);
                tile_update(Apk, psolT, k0 + 16 + ti * 4, k0 + 16 + tj * 4);
            }
        }
        __syncthreads();

        // panel solve kb (rows k0+16..127)
        if (rem > 0) {
            if (tid < rem) {
                const int i = k0 + 16 + tid;
                const int ro = aoff(i) + k0;
                float r[16];
                #pragma unroll
                for (int c4 = 0; c4 < 4; ++c4) {
                    float4 v = *reinterpret_cast<const float4*>(&Apk[ro + c4 * 4]);
                    r[c4 * 4 + 0] = v.x; r[c4 * 4 + 1] = v.y;
                    r[c4 * 4 + 2] = v.z; r[c4 * 4 + 3] = v.w;
                }
                #pragma unroll
                for (int c = 0; c < 16; ++c) {
                    float s = 0.0f;
                    #pragma unroll
                    for (int d = 0; d <= c; ++d)
                        s = fmaf(invL[c * 17 + d], r[d], s);
                    Apk[ro + c] = s;
                    psolT[c * 132 + i] = s;
                }
            }
            __syncthreads();
        }
    }

    // ---- write chol: full row per thread (lower values, zeros above) ----
    {
        const int i = tid;
        const int ro = aoff(i);
        float* crow = c_out + i * 128;
        for (int c4 = 0; c4 < 32; ++c4) {
            const int j0 = c4 * 4;
            float va[4];
            #pragma unroll
            for (int c = 0; c < 4; ++c)
                va[c] = (j0 + c <= i) ? Apk[ro + j0 + c] : 0.0f;
            *reinterpret_cast<float4*>(crow + j0) =
                make_float4(va[0], va[1], va[2], va[3]);
        }
    }
}

extern "C" void kernel_launch(void* const* d_in, const int* in_sizes, int n_in,
                              void* d_out, int out_size)
{
    const float* aug      = (const float*)d_in[0];
    const float* theta    = (const float*)d_in[1];
    const float* scales   = (const float*)d_in[2];
    const float* nug_mean = (const float*)d_in[3];
    const int*   bidx     = (const int*)d_in[4];
    float* out = (float*)d_out;

    gram_kernel<<<N_LOC, 512>>>(aug, theta, scales, nug_mean, bidx, out);
    chol_kernel<<<N_LOC, 128>>>(out);
}

// round 13
// speedup vs baseline: 1.4712x; 1.0063x over previous
#include <cuda_runtime.h>
#include <math.h>

#define N_LOC 4096
#define N_REP 128
#define M_NBR 48

// packed lower-triangle row offset (rows padded to multiples of 4)
__device__ __forceinline__ int aoff(int i) {
    int q = i >> 2;
    return 4 * (q + 1) * (2 * q + (i & 3));
}

__device__ __forceinline__ void tridec(int t, int& row, int& col) {
    int r = (int)((sqrtf(8.0f * (float)t + 1.0f) - 1.0f) * 0.5f);
    while ((r + 1) * (r + 2) / 2 <= t) ++r;
    while (r * (r + 1) / 2 > t) --r;
    row = r;
    col = t - r * (r + 1) / 2;
}

// ===================== Kernel 1: gram + Matern epilogue -> g =====================
__global__ __launch_bounds__(512, 3)
void gram_kernel(const float* __restrict__ aug,
                 const float* __restrict__ theta,
                 const float* __restrict__ scales,
                 const float* __restrict__ nug_mean,
                 const int* __restrict__ batch_idx,
                 float* __restrict__ out)
{
    const int N = blockIdx.x;
    const int tid = threadIdx.x;
    float* g_out = out + (size_t)N * 16384;

    if (batch_idx[N] == 0) {
        for (int idx = tid; idx < 16384; idx += 512)
            g_out[idx] = ((idx >> 7) == (idx & 127)) ? 1.0f : 0.0f;
        return;
    }

    __shared__ float xs[M_NBR * 128];
    __shared__ float diag[128];
    __shared__ float scalm[M_NBR];

    const float t2 = theta[2];
    const float t3 = theta[3];
    const float t4 = theta[4];
    const float t5 = theta[5];
    const float ls = expf(t5) * 1.7320508075688772f;
    const float inv_ls2 = 1.0f / (ls * ls);
    const float sig2 = expf(2.0f * (logf(scales[N]) * t4 + t3));
    const float inv_nug = 1.0f / nug_mean[N];

    if (tid < M_NBR)
        scalm[tid] = expf(-0.5f * (float)(tid + 1) * expf(t2));
    __syncthreads();

    {
        const float* base = aug + (size_t)N * (M_NBR + 1) + 1;
        for (int idx = tid; idx < N_REP * M_NBR; idx += 512) {
            int i = idx / M_NBR;
            int m = idx - i * M_NBR;
            float v = base[(size_t)i * ((size_t)N_LOC * (M_NBR + 1)) + m];
            if (v != v) v = 0.0f;
            xs[m * 128 + i] = v * scalm[m];
        }
    }
    __syncthreads();

    if (tid < N_REP) {
        float d = 0.0f;
        #pragma unroll
        for (int m = 0; m < M_NBR; ++m) {
            float v = xs[m * 128 + tid];
            d = fmaf(v, v, d);
        }
        diag[tid] = d;
    }
    __syncthreads();

    for (int t = tid; t < 528; t += 512) {
        int ti, tj;
        tridec(t, ti, tj);
        const int ib = ti * 4, jb = tj * 4;

        float acc[16];
        #pragma unroll
        for (int k = 0; k < 16; ++k) acc[k] = 0.0f;

        #pragma unroll 4
        for (int m = 0; m < M_NBR; ++m) {
            const float* row = xs + m * 128;
            float4 a = *reinterpret_cast<const float4*>(row + ib);
            float4 b = *reinterpret_cast<const float4*>(row + jb);
            float av[4] = {a.x, a.y, a.z, a.w};
            float bv[4] = {b.x, b.y, b.z, b.w};
            #pragma unroll
            for (int r = 0; r < 4; ++r)
                #pragma unroll
                for (int c = 0; c < 4; ++c)
                    acc[r * 4 + c] = fmaf(av[r], bv[c], acc[r * 4 + c]);
        }

        float di[4], dj[4];
        #pragma unroll
        for (int r = 0; r < 4; ++r) di[r] = diag[ib + r];
        #pragma unroll
        for (int c = 0; c < 4; ++c) dj[c] = diag[jb + c];

        #pragma unroll
        for (int r = 0; r < 4; ++r)
            #pragma unroll
            for (int c = 0; c < 4; ++c) {
                float G = acc[r * 4 + c];
                float sq = fmaxf((di[r] + dj[c] - 2.0f * G) * inv_ls2, 0.0f);
                float s3 = 1.7320508075688772f * sq * __frsqrt_rn(fmaxf(sq, 1e-30f));
                float mat = (1.0f + s3) * __expf(-s3);
                acc[r * 4 + c] = (G + sig2 * mat) * inv_nug
                               + ((ib + r == jb + c) ? 1.0f : 0.0f);
            }

        #pragma unroll
        for (int r = 0; r < 4; ++r)
            *reinterpret_cast<float4*>(g_out + (ib + r) * 128 + jb) =
                make_float4(acc[r * 4], acc[r * 4 + 1], acc[r * 4 + 2], acc[r * 4 + 3]);
        if (ti > tj) {
            #pragma unroll
            for (int c = 0; c < 4; ++c)
                *reinterpret_cast<float4*>(g_out + (jb + c) * 128 + ib) =
                    make_float4(acc[c], acc[4 + c], acc[8 + c], acc[12 + c]);
        }
    }
}

// ===================== Kernel 2: batched Cholesky ===============================

#define NTAB 1106   // total precomputed tiles for kb=1..6

// per-thread rank-16 update of 4x4 tile (ib,jb); panel read from Apk cols [kp,kp+16)
__device__ __forceinline__ void tile_update(float* __restrict__ Apk, int ib, int jb, int kp)
{
    int roi[4], roj[4];
    #pragma unroll
    for (int r = 0; r < 4; ++r) {
        roi[r] = aoff(ib + r) + kp;
        roj[r] = aoff(jb + r) + kp;
    }
    float acc[16];
    #pragma unroll
    for (int k = 0; k < 16; ++k) acc[k] = 0.0f;

    #pragma unroll
    for (int q = 0; q < 4; ++q) {
        float4 a4[4], b4[4];
        #pragma unroll
        for (int r = 0; r < 4; ++r) {
            a4[r] = *reinterpret_cast<const float4*>(&Apk[roi[r] + q * 4]);
            b4[r] = *reinterpret_cast<const float4*>(&Apk[roj[r] + q * 4]);
        }
        #pragma unroll
        for (int r = 0; r < 4; ++r)
            #pragma unroll
            for (int s = 0; s < 4; ++s) {
                float a = acc[r * 4 + s];
                a = fmaf(a4[r].x, b4[s].x, a);
                a = fmaf(a4[r].y, b4[s].y, a);
                a = fmaf(a4[r].z, b4[s].z, a);
                a = fmaf(a4[r].w, b4[s].w, a);
                acc[r * 4 + s] = a;
            }
    }

    #pragma unroll
    for (int r = 0; r < 4; ++r) {
        const int i = ib + r;
        const int ro = aoff(i);
        if (jb + 3 <= i) {
            float4 a = *reinterpret_cast<float4*>(&Apk[ro + jb]);
            a.x -= acc[r * 4 + 0];
            a.y -= acc[r * 4 + 1];
            a.z -= acc[r * 4 + 2];
            a.w -= acc[r * 4 + 3];
            *reinterpret_cast<float4*>(&Apk[ro + jb]) = a;
        } else {
            #pragma unroll
            for (int s = 0; s < 4; ++s) {
                const int j = jb + s;
                if (j <= i) Apk[ro + j] -= acc[r * 4 + s];
            }
        }
    }
}

// warp0: factor 16x16 diag block at k0 (in Apk), produce invd + invL.
__device__ __forceinline__ void diag_factor(float* __restrict__ Apk,
                                            float* __restrict__ invd,
                                            float* __restrict__ invL,
                                            int k0, int lane)
{
    float rw[16];
    const int ro = (lane < 16) ? (aoff(k0 + lane) + k0) : 0;
    if (lane < 16) {
        #pragma unroll
        for (int j = 0; j < 16; ++j)
            rw[j] = (j <= lane) ? Apk[ro + j] : 0.0f;
    } else {
        #pragma unroll
        for (int j = 0; j < 16; ++j) rw[j] = 0.0f;
    }
    #pragma unroll
    for (int c = 0; c < 16; ++c) {
        float dcc = __shfl_sync(0xffffffffu, rw[c], c);
        float lcc = sqrtf(dcc);
        float inv = 1.0f / lcc;
        if (lane == c) { rw[c] = lcc; invd[c] = inv; }
        else if (lane > c && lane < 16) rw[c] *= inv;
        float vc = rw[c];
        #pragma unroll
        for (int j = c + 1; j < 16; ++j) {
            float vj = __shfl_sync(0xffffffffu, vc, j);
            if (lane >= j && lane < 16) rw[j] -= vc * vj;
        }
    }
    if (lane < 16) {
        #pragma unroll
        for (int j = 0; j < 16; ++j)
            if (j <= lane) Apk[ro + j] = rw[j];
    }
    __syncwarp();
    // inv(L11) column `lane`
    if (lane < 16) {
        float x[16];
        #pragma unroll
        for (int r = 0; r < 16; ++r) {
            float s = (r == lane) ? 1.0f : 0.0f;
            const int rr = aoff(k0 + r) + k0;
            #pragma unroll
            for (int d = 0; d < r; ++d)
                s -= Apk[rr + d] * x[d];
            x[r] = s * invd[r];
            invL[r * 17 + lane] = x[r];
        }
    }
}

__global__ __launch_bounds__(128, 6)
void chol_kernel(float* __restrict__ out)
{
    const int N = blockIdx.x;
    const int tid = threadIdx.x;
    const int wrp = tid >> 5;
    const int lane = tid & 31;
    const float* g_in = out + (size_t)N * 16384;
    float* c_out = out + (size_t)N_LOC * 16384 + (size_t)N * 16384;

    __shared__ float Apk[8448];        // packed lower triangle
    __shared__ float invd[16];
    __shared__ float invL[16 * 17];
    __shared__ uchar2 ttab[NTAB];      // precomputed (ib,jb) tiles for kb=1..6

    // per-kb start offsets into ttab (kb=1..7); counts: 396,290,200,126,68,26,0
    // NOTE: 9 entries — tstart[kb+1] at kb=7 must be valid (cnt = 0).
    const int tstart[9] = {0, 0, 396, 686, 886, 1012, 1080, 1106, 1106};

    // ---- fill tile table ----
    for (int idx = tid; idx < NTAB; idx += 128) {
        int off = idx;
        int k = 1;
        #pragma unroll 1
        for (int kk = 1; kk <= 6; ++kk) {
            const int nr = 28 - 4 * kk;
            const int cnt = nr * 4 + nr * (nr + 1) / 2;
            if (off < cnt) { k = kk; break; }
            off -= cnt;
        }
        const int k0 = k * 16;
        const int nrows = 28 - 4 * k;
        const int pc = nrows * 4;
        int ib, jb;
        if (off < pc) {
            ib = k0 + 16 + (off >> 2) * 4;
            jb = k0 + (off & 3) * 4;
        } else {
            int t = off - pc, ti, tj;
            tridec(t, ti, tj);
            ib = k0 + 16 + ti * 4;
            jb = k0 + 16 + tj * 4;
        }
        ttab[idx] = make_uchar2((unsigned char)ib, (unsigned char)jb);
    }

    // ---- load lower triangle of g into packed smem; thread = row ----
    {
        const int i = tid;
        const int ro = aoff(i);
        const int nch = (i >> 2) + 1;
        const float* grow = g_in + i * 128;
        for (int c4 = 0; c4 < nch; ++c4)
            *reinterpret_cast<float4*>(&Apk[ro + c4 * 4]) =
                *reinterpret_cast<const float4*>(grow + c4 * 4);
    }
    __syncthreads();

    // ---- kb = 0: factor diag block 0 ----
    if (wrp == 0) diag_factor(Apk, invd, invL, 0, lane);
    __syncthreads();

    // ---- panel solve 0 (rows 16..127) ----
    if (tid < 112) {
        const int i = 16 + tid;
        const int ro = aoff(i);
        float r[16];
        #pragma unroll
        for (int c4 = 0; c4 < 4; ++c4) {
            float4 v = *reinterpret_cast<const float4*>(&Apk[ro + c4 * 4]);
            r[c4 * 4 + 0] = v.x; r[c4 * 4 + 1] = v.y;
            r[c4 * 4 + 2] = v.z; r[c4 * 4 + 3] = v.w;
        }
        #pragma unroll
        for (int c = 0; c < 16; ++c) {
            float s = 0.0f;
            #pragma unroll
            for (int d = 0; d <= c; ++d)
                s = fmaf(invL[c * 17 + d], r[d], s);
            Apk[ro + c] = s;
        }
    }
    __syncthreads();

    // ---- kb = 1..7: fused [warp0: diag-update+factor || warps1-3: all updates] ----
    #pragma unroll 1
    for (int kb = 1; kb < 8; ++kb) {
        const int k0 = kb * 16;
        const int kp = k0 - 16;           // panel column base (solved in prev phase)
        const int rem = 112 - k0;

        if (wrp == 0) {
            // update the 10 diag-block tiles, then factor the block
            if (lane < 10) {
                int ti, tj;
                tridec(lane, ti, tj);
                tile_update(Apk, k0 + ti * 4, k0 + tj * 4, kp);
            }
            __syncwarp();
            diag_factor(Apk, invd, invL, k0, lane);
        } else {
            // all remaining updates for this kb from the precomputed table
            const int base = tstart[kb];
            const int cnt = tstart[kb + 1] - base;
            for (int e = tid - 32; e < cnt; e += 96) {
                uchar2 tt = ttab[base + e];
                tile_update(Apk, (int)tt.x, (int)tt.y, kp);
            }
        }
        __syncthreads();

        // panel solve kb (rows k0+16..127)
        if (rem > 0) {
            if (tid < rem) {
                const int i = k0 + 16 + tid;
                const int ro = aoff(i) + k0;
                float r[16];
                #pragma unroll
                for (int c4 = 0; c4 < 4; ++c4) {
                    float4 v = *reinterpret_cast<const float4*>(&Apk[ro + c4 * 4]);
                    r[c4 * 4 + 0] = v.x; r[c4 * 4 + 1] = v.y;
                    r[c4 * 4 + 2] = v.z; r[c4 * 4 + 3] = v.w;
                }
                #pragma unroll
                for (int c = 0; c < 16; ++c) {
                    float s = 0.0f;
                    #pragma unroll
                    for (int d = 0; d <= c; ++d)
                        s = fmaf(invL[c * 17 + d], r[d], s);
                    Apk[ro + c] = s;
                }
            }
            __syncthreads();
        }
    }
    __syncthreads();

    // ---- write chol: full row per thread (lower values, zeros above) ----
    {
        const int i = tid;
        const int ro = aoff(i);
        float* crow = c_out + i * 128;
        for (int c4 = 0; c4 < 32; ++c4) {
            const int j0 = c4 * 4;
            float va[4];
            #pragma unroll
            for (int c = 0; c < 4; ++c)
                va[c] = (j0 + c <= i) ? Apk[ro + j0 + c] : 0.0f;
            *reinterpret_cast<float4*>(crow + j0) =
                make_float4(va[0], va[1], va[2], va[3]);
        }
    }
}

extern "C" void kernel_launch(void* const* d_in, const int* in_sizes, int n_in,
                              void* d_out, int out_size)
{
    const float* aug      = (const float*)d_in[0];
    const float* theta    = (const float*)d_in[1];
    const float* scales   = (const float*)d_in[2];
    const float* nug_mean = (const float*)d_in[3];
    const int*   bidx     = (const int*)d_in[4];
    float* out = (float*)d_out;

    gram_kernel<<<N_LOC, 512>>>(aug, theta, scales, nug_mean, bidx, out);
    chol_kernel<<<N_LOC, 128>>>(out);
}

// round 14
// speedup vs baseline: 1.5980x; 1.0861x over previous
#include <cuda_runtime.h>
#include <math.h>

#define N_LOC 4096
#define N_REP 128
#define M_NBR 48

// packed lower-triangle row offset (rows padded to multiples of 4)
__device__ __forceinline__ int aoff(int i) {
    int q = i >> 2;
    return 4 * (q + 1) * (2 * q + (i & 3));
}

__device__ __forceinline__ void tridec(int t, int& row, int& col) {
    int r = (int)((sqrtf(8.0f * (float)t + 1.0f) - 1.0f) * 0.5f);
    while ((r + 1) * (r + 2) / 2 <= t) ++r;
    while (r * (r + 1) / 2 > t) --r;
    row = r;
    col = t - r * (r + 1) / 2;
}

// ===================== Kernel 1: gram + Matern epilogue -> g =====================
__global__ __launch_bounds__(512, 3)
void gram_kernel(const float* __restrict__ aug,
                 const float* __restrict__ theta,
                 const float* __restrict__ scales,
                 const float* __restrict__ nug_mean,
                 const int* __restrict__ batch_idx,
                 float* __restrict__ out)
{
    const int N = blockIdx.x;
    const int tid = threadIdx.x;
    float* g_out = out + (size_t)N * 16384;

    if (batch_idx[N] == 0) {
        for (int idx = tid; idx < 16384; idx += 512)
            g_out[idx] = ((idx >> 7) == (idx & 127)) ? 1.0f : 0.0f;
        return;
    }

    __shared__ float xs[M_NBR * 128];
    __shared__ float diag[128];
    __shared__ float scalm[M_NBR];

    const float t2 = theta[2];
    const float t3 = theta[3];
    const float t4 = theta[4];
    const float t5 = theta[5];
    const float ls = expf(t5) * 1.7320508075688772f;
    const float inv_ls2 = 1.0f / (ls * ls);
    const float sig2 = expf(2.0f * (logf(scales[N]) * t4 + t3));
    const float inv_nug = 1.0f / nug_mean[N];

    if (tid < M_NBR)
        scalm[tid] = expf(-0.5f * (float)(tid + 1) * expf(t2));
    __syncthreads();

    {
        const float* base = aug + (size_t)N * (M_NBR + 1) + 1;
        for (int idx = tid; idx < N_REP * M_NBR; idx += 512) {
            int i = idx / M_NBR;
            int m = idx - i * M_NBR;
            float v = base[(size_t)i * ((size_t)N_LOC * (M_NBR + 1)) + m];
            if (v != v) v = 0.0f;
            xs[m * 128 + i] = v * scalm[m];
        }
    }
    __syncthreads();

    if (tid < N_REP) {
        float d = 0.0f;
        #pragma unroll
        for (int m = 0; m < M_NBR; ++m) {
            float v = xs[m * 128 + tid];
            d = fmaf(v, v, d);
        }
        diag[tid] = d;
    }
    __syncthreads();

    for (int t = tid; t < 528; t += 512) {
        int ti, tj;
        tridec(t, ti, tj);
        const int ib = ti * 4, jb = tj * 4;

        float acc[16];
        #pragma unroll
        for (int k = 0; k < 16; ++k) acc[k] = 0.0f;

        #pragma unroll 4
        for (int m = 0; m < M_NBR; ++m) {
            const float* row = xs + m * 128;
            float4 a = *reinterpret_cast<const float4*>(row + ib);
            float4 b = *reinterpret_cast<const float4*>(row + jb);
            float av[4] = {a.x, a.y, a.z, a.w};
            float bv[4] = {b.x, b.y, b.z, b.w};
            #pragma unroll
            for (int r = 0; r < 4; ++r)
                #pragma unroll
                for (int c = 0; c < 4; ++c)
                    acc[r * 4 + c] = fmaf(av[r], bv[c], acc[r * 4 + c]);
        }

        float di[4], dj[4];
        #pragma unroll
        for (int r = 0; r < 4; ++r) di[r] = diag[ib + r];
        #pragma unroll
        for (int c = 0; c < 4; ++c) dj[c] = diag[jb + c];

        #pragma unroll
        for (int r = 0; r < 4; ++r)
            #pragma unroll
            for (int c = 0; c < 4; ++c) {
                float G = acc[r * 4 + c];
                float sq = fmaxf((di[r] + dj[c] - 2.0f * G) * inv_ls2, 0.0f);
                float s3 = 1.7320508075688772f * sq * __frsqrt_rn(fmaxf(sq, 1e-30f));
                float mat = (1.0f + s3) * __expf(-s3);
                acc[r * 4 + c] = (G + sig2 * mat) * inv_nug
                               + ((ib + r == jb + c) ? 1.0f : 0.0f);
            }

        #pragma unroll
        for (int r = 0; r < 4; ++r)
            *reinterpret_cast<float4*>(g_out + (ib + r) * 128 + jb) =
                make_float4(acc[r * 4], acc[r * 4 + 1], acc[r * 4 + 2], acc[r * 4 + 3]);
        if (ti > tj) {
            #pragma unroll
            for (int c = 0; c < 4; ++c)
                *reinterpret_cast<float4*>(g_out + (jb + c) * 128 + ib) =
                    make_float4(acc[c], acc[4 + c], acc[8 + c], acc[12 + c]);
        }
    }
}

// ===================== Kernel 2: batched Cholesky ===============================

// Warp-cooperative rank-16 update of the 16x16 block (I,J) using panel cols
// [kp, kp+16). Panel blocks held in registers; inner loop uses shuffles only.
// Lane layout: lr = lane>>3 (out rows 4lr..+3), lc = lane&7 (out cols 2lc..+1).
// A[row_local][d] is held by lane (row_local<<1)|(d>>3), register index d&7.
__device__ __forceinline__ void warp_block_update(float* __restrict__ Apk,
                                                  int I, int J, int kp,
                                                  int lane, bool isdiag)
{
    const int lr = lane >> 3;
    const int lc = lane & 7;
    const int lrow = lane >> 1;            // local row loaded by this lane
    const int h8 = (lane & 1) << 3;        // column half (0 or 8)

    float areg[8], breg[8];
    {
        const float* p = &Apk[aoff((I << 4) + lrow) + kp + h8];
        float4 v0 = *reinterpret_cast<const float4*>(p);
        float4 v1 = *reinterpret_cast<const float4*>(p + 4);
        areg[0] = v0.x; areg[1] = v0.y; areg[2] = v0.z; areg[3] = v0.w;
        areg[4] = v1.x; areg[5] = v1.y; areg[6] = v1.z; areg[7] = v1.w;
    }
    if (isdiag) {
        #pragma unroll
        for (int q = 0; q < 8; ++q) breg[q] = areg[q];
    } else {
        const float* p = &Apk[aoff((J << 4) + lrow) + kp + h8];
        float4 v0 = *reinterpret_cast<const float4*>(p);
        float4 v1 = *reinterpret_cast<const float4*>(p + 4);
        breg[0] = v0.x; breg[1] = v0.y; breg[2] = v0.z; breg[3] = v0.w;
        breg[4] = v1.x; breg[5] = v1.y; breg[6] = v1.z; breg[7] = v1.w;
    }

    float acc[8];
    #pragma unroll
    for (int k = 0; k < 8; ++k) acc[k] = 0.0f;

    const int ra = lr << 2;   // first out row (local)
    const int ca = lc << 1;   // first out col (local)

    #pragma unroll
    for (int d = 0; d < 16; ++d) {
        const int dh = d >> 3;
        const int di = d & 7;
        float a0 = __shfl_sync(0xffffffffu, areg[di], ((ra + 0) << 1) | dh);
        float a1 = __shfl_sync(0xffffffffu, areg[di], ((ra + 1) << 1) | dh);
        float a2 = __shfl_sync(0xffffffffu, areg[di], ((ra + 2) << 1) | dh);
        float a3 = __shfl_sync(0xffffffffu, areg[di], ((ra + 3) << 1) | dh);
        float b0 = __shfl_sync(0xffffffffu, breg[di], ((ca + 0) << 1) | dh);
        float b1 = __shfl_sync(0xffffffffu, breg[di], ((ca + 1) << 1) | dh);
        acc[0] = fmaf(a0, b0, acc[0]); acc[1] = fmaf(a0, b1, acc[1]);
        acc[2] = fmaf(a1, b0, acc[2]); acc[3] = fmaf(a1, b1, acc[3]);
        acc[4] = fmaf(a2, b0, acc[4]); acc[5] = fmaf(a2, b1, acc[5]);
        acc[6] = fmaf(a3, b0, acc[6]); acc[7] = fmaf(a3, b1, acc[7]);
    }

    const int ob = (J << 4) + ca;
    #pragma unroll
    for (int r = 0; r < 4; ++r) {
        const int il = ra + r;
        float* p = &Apk[aoff((I << 4) + il) + ob];
        if (!isdiag) {
            float2 v = *reinterpret_cast<float2*>(p);
            v.x -= acc[r * 2 + 0];
            v.y -= acc[r * 2 + 1];
            *reinterpret_cast<float2*>(p) = v;
        } else {
            if (ca     <= il) p[0] -= acc[r * 2 + 0];
            if (ca + 1 <= il) p[1] -= acc[r * 2 + 1];
        }
    }
}

// warp0: factor 16x16 diag block at k0 (in Apk), produce invd + invL.
__device__ __forceinline__ void diag_factor(float* __restrict__ Apk,
                                            float* __restrict__ invd,
                                            float* __restrict__ invL,
                                            int k0, int lane)
{
    float rw[16];
    const int ro = (lane < 16) ? (aoff(k0 + lane) + k0) : 0;
    if (lane < 16) {
        #pragma unroll
        for (int j = 0; j < 16; ++j)
            rw[j] = (j <= lane) ? Apk[ro + j] : 0.0f;
    } else {
        #pragma unroll
        for (int j = 0; j < 16; ++j) rw[j] = 0.0f;
    }
    #pragma unroll
    for (int c = 0; c < 16; ++c) {
        float dcc = __shfl_sync(0xffffffffu, rw[c], c);
        float lcc = sqrtf(dcc);
        float inv = 1.0f / lcc;
        if (lane == c) { rw[c] = lcc; invd[c] = inv; }
        else if (lane > c && lane < 16) rw[c] *= inv;
        float vc = rw[c];
        #pragma unroll
        for (int j = c + 1; j < 16; ++j) {
            float vj = __shfl_sync(0xffffffffu, vc, j);
            if (lane >= j && lane < 16) rw[j] -= vc * vj;
        }
    }
    if (lane < 16) {
        #pragma unroll
        for (int j = 0; j < 16; ++j)
            if (j <= lane) Apk[ro + j] = rw[j];
    }
    __syncwarp();
    // inv(L11) column `lane`
    if (lane < 16) {
        float x[16];
        #pragma unroll
        for (int r = 0; r < 16; ++r) {
            float s = (r == lane) ? 1.0f : 0.0f;
            const int rr = aoff(k0 + r) + k0;
            #pragma unroll
            for (int d = 0; d < r; ++d)
                s -= Apk[rr + d] * x[d];
            x[r] = s * invd[r];
            invL[r * 17 + lane] = x[r];
        }
    }
}

__global__ __launch_bounds__(128, 6)
void chol_kernel(float* __restrict__ out)
{
    const int N = blockIdx.x;
    const int tid = threadIdx.x;
    const int wrp = tid >> 5;
    const int lane = tid & 31;
    const float* g_in = out + (size_t)N * 16384;
    float* c_out = out + (size_t)N_LOC * 16384 + (size_t)N * 16384;

    __shared__ float Apk[8448];        // packed lower triangle
    __shared__ float invd[16];
    __shared__ float invL[16 * 17];

    // ---- load lower triangle of g into packed smem; thread = row ----
    {
        const int i = tid;
        const int ro = aoff(i);
        const int nch = (i >> 2) + 1;
        const float* grow = g_in + i * 128;
        for (int c4 = 0; c4 < nch; ++c4)
            *reinterpret_cast<float4*>(&Apk[ro + c4 * 4]) =
                *reinterpret_cast<const float4*>(grow + c4 * 4);
    }
    __syncthreads();

    // ---- kb = 0: factor diag block 0 ----
    if (wrp == 0) diag_factor(Apk, invd, invL, 0, lane);
    __syncthreads();

    // ---- panel solve 0 (rows 16..127) ----
    if (tid < 112) {
        const int i = 16 + tid;
        const int ro = aoff(i);
        float r[16];
        #pragma unroll
        for (int c4 = 0; c4 < 4; ++c4) {
            float4 v = *reinterpret_cast<const float4*>(&Apk[ro + c4 * 4]);
            r[c4 * 4 + 0] = v.x; r[c4 * 4 + 1] = v.y;
            r[c4 * 4 + 2] = v.z; r[c4 * 4 + 3] = v.w;
        }
        #pragma unroll
        for (int c = 0; c < 16; ++c) {
            float s = 0.0f;
            #pragma unroll
            for (int d = 0; d <= c; ++d)
                s = fmaf(invL[c * 17 + d], r[d], s);
            Apk[ro + c] = s;
        }
    }
    __syncthreads();

    // ---- kb = 1..7: [warp0: diag block update + factor || warps1-3: all other
    //      16x16 block tasks], then panel solve ----
    #pragma unroll 1
    for (int kb = 1; kb < 8; ++kb) {
        const int k0 = kb * 16;
        const int kp = k0 - 16;           // panel column base (solved last phase)
        const int rem = 112 - k0;
        const int B = 8 - kb;             // trailing block count (incl diag)
        const int ntasks = B * (B + 1) / 2;

        if (wrp == 0) {
            // task 0 = (kb,kb): update then factor
            warp_block_update(Apk, kb, kb, kp, lane, true);
            __syncwarp();
            diag_factor(Apk, invd, invL, k0, lane);
        } else {
            for (int t = wrp; t < ntasks; t += 3) {
                int bi, bj;
                tridec(t, bi, bj);
                warp_block_update(Apk, kb + bi, kb + bj, kp, lane, bi == bj);
            }
        }
        __syncthreads();

        // panel solve kb (rows k0+16..127)
        if (rem > 0) {
            if (tid < rem) {
                const int i = k0 + 16 + tid;
                const int ro = aoff(i) + k0;
                float r[16];
                #pragma unroll
                for (int c4 = 0; c4 < 4; ++c4) {
                    float4 v = *reinterpret_cast<const float4*>(&Apk[ro + c4 * 4]);
                    r[c4 * 4 + 0] = v.x; r[c4 * 4 + 1] = v.y;
                    r[c4 * 4 + 2] = v.z; r[c4 * 4 + 3] = v.w;
                }
                #pragma unroll
                for (int c = 0; c < 16; ++c) {
                    float s = 0.0f;
                    #pragma unroll
                    for (int d = 0; d <= c; ++d)
                        s = fmaf(invL[c * 17 + d], r[d], s);
                    Apk[ro + c] = s;
                }
            }
            __syncthreads();
        }
    }
    __syncthreads();

    // ---- write chol: full row per thread (lower values, zeros above) ----
    {
        const int i = tid;
        const int ro = aoff(i);
        float* crow = c_out + i * 128;
        for (int c4 = 0; c4 < 32; ++c4) {
            const int j0 = c4 * 4;
            float va[4];
            #pragma unroll
            for (int c = 0; c < 4; ++c)
                va[c] = (j0 + c <= i) ? Apk[ro + j0 + c] : 0.0f;
            *reinterpret_cast<float4*>(crow + j0) =
                make_float4(va[0], va[1], va[2], va[3]);
        }
    }
}

extern "C" void kernel_launch(void* const* d_in, const int* in_sizes, int n_in,
                              void* d_out, int out_size)
{
    const float* aug      = (const float*)d_in[0];
    const float* theta    = (const float*)d_in[1];
    const float* scales   = (const float*)d_in[2];
    const float* nug_mean = (const float*)d_in[3];
    const int*   bidx     = (const int*)d_in[4];
    float* out = (float*)d_out;

    gram_kernel<<<N_LOC, 512>>>(aug, theta, scales, nug_mean, bidx, out);
    chol_kernel<<<N_LOC, 128>>>(out);
}